// round 13
// baseline (speedup 1.0000x reference)
#include <cuda_runtime.h>

// GaussianBlurDM, round 12: immediate-weight convolution.
//
// out[b] = reflect-conv(reflect-conv(x[b], K_t, axis=H), K_t, axis=W),
// K_t = t-fold self-convolution of the 11-tap Gaussian (exact DCT-I identity),
// truncated at tail mass 5e-4 (exact odd tap count, no padding).
//
// Key change vs R11: weights are compile-time constants (constexpr table),
// and the interior conv paths are template-unrolled per t so every MAC is
// FFMA Rd,Rs,IMM,Rc  -- rt_SMSP=1 vs fma.rn.f32x2's banking-limited rt=3
// (3 distinct even + 3 distinct odd operand registers). 1.5x the MAC rate,
// no weight LDC, no loop overhead. Boundary work (~25%) uses one shared
// __noinline__ runtime-weight path.

#define BATCH 64
#define CHAN 3
#define IMG 256
#define NT 19
#define KW 80              // weight array length (nd <= ~66)
#define SVSTRIDE 18        // floats per sv column (16 rows + 2 pad)

// ---------------------------------------------------------------------------
// Compile-time weight table.
// ---------------------------------------------------------------------------
struct KTab {
    float w[NT][KW];
    int nd[NT];
    int rl[NT];
};

constexpr KTab make_ktab() {
    KTab T{};
    // q = e^{-1/8} by Taylor (full double precision)
    double q = 1.0;
    {
        double term = 1.0;
        for (int i = 1; i < 26; ++i) { term *= (-0.125) / (double)i; q += term; }
    }
    // base pdf[x] = q^(x^2), x = -5..5 ; f32-rounded normalized (matches _k1d)
    double base[11] = {};
    double sum = 0.0;
    for (int x = -5; x <= 5; ++x) {
        double p = 1.0;
        for (int i = 0; i < x * x; ++i) p *= q;
        base[x + 5] = p;
        sum += p;
    }
    for (int i = 0; i < 11; ++i) base[i] = (double)((float)(base[i] / sum));

    double f[220] = {};
    for (int i = 0; i < 11; ++i) f[i] = base[i];
    int hw = 5;
    for (int tt = 1; tt <= NT; ++tt) {
        double acc = 0.0;
        int r = 0;
        for (int a = hw; a >= 1; --a) {
            acc += f[hw + a];
            if (2.0 * acc > 5e-4) { r = a; break; }
        }
        T.nd[tt - 1] = 2 * r + 1;
        T.rl[tt - 1] = r;
        for (int j = 0; j <= 2 * r; ++j) T.w[tt - 1][j] = (float)f[hw + j - r];
        if (tt < NT) {                       // f = f (*) base
            double g[220] = {};
            int L = 2 * hw + 1;
            for (int n = 0; n < L; ++n) {
                double fn = f[n];
                for (int k = 0; k < 11; ++k) g[n + k] += fn * base[k];
            }
            for (int i = 0; i < 220; ++i) f[i] = g[i];
            hw += 5;
        }
    }
    return T;
}
constexpr KTab KT = make_ktab();

struct BlurParams { float K[NT][KW]; };   // runtime copy for boundary paths

__device__ __forceinline__ int reflect256(int v) {
    v = abs(v);
    return (v > 255) ? (510 - v) : v;
}

// ---------------------------------------------------------------------------
// Template-recursive unrolled tap loops (weights become FFMA immediates).
// acc[k].x/.y = two adjacent units along the non-conv axis.
// ---------------------------------------------------------------------------
template<int TI, int J>
struct VTap {
    static __device__ __forceinline__ void run(
        float2 (&acc)[8], float2 (&ring)[8], const float2* __restrict__ p)
    {
        constexpr float W = KT.w[TI][J];
        #pragma unroll
        for (int k = 0; k < 8; ++k) {
            float2 r = ring[(J + k) & 7];
            acc[k].x = fmaf(r.x, W, acc[k].x);
            acc[k].y = fmaf(r.y, W, acc[k].y);
        }
        if constexpr (J + 8 < KT.nd[TI] + 7)
            ring[J & 7] = __ldg(p + ((J + 8) << 7));     // row stride 128 f2
        if constexpr (J + 1 < KT.nd[TI])
            VTap<TI, J + 1>::run(acc, ring, p);
    }
};

template<int TI, int J>
struct HTap {
    static __device__ __forceinline__ void run(
        float2 (&acc)[8], float2 (&ring)[8], const float2* __restrict__ p)
    {
        constexpr float W = KT.w[TI][J];
        #pragma unroll
        for (int k = 0; k < 8; ++k) {
            float2 r = ring[(J + k) & 7];
            acc[k].x = fmaf(r.x, W, acc[k].x);
            acc[k].y = fmaf(r.y, W, acc[k].y);
        }
        if constexpr (J + 8 < KT.nd[TI] + 7)
            ring[J & 7] = p[(J + 8) * (SVSTRIDE / 2)];   // smem col stride
        if constexpr (J + 1 < KT.nd[TI])
            HTap<TI, J + 1>::run(acc, ring, p);
    }
};

// ---------------------------------------------------------------------------
// Shared epilogues.
// ---------------------------------------------------------------------------
__device__ __forceinline__ void store_sv(float* sv, int cp_, int half,
                                         const float2 (&acc)[8])
{
    const int c0 = cp_ << 1;
    float* q0 = sv + c0 * SVSTRIDE + (half << 3);
    float* q1 = sv + (c0 + 1) * SVSTRIDE + (half << 3);
    #pragma unroll
    for (int q = 0; q < 4; ++q) {
        *(float2*)(q0 + 2 * q) = make_float2(acc[2 * q].x, acc[2 * q + 1].x);
        *(float2*)(q1 + 2 * q) = make_float2(acc[2 * q].y, acc[2 * q + 1].y);
    }
}

__device__ __forceinline__ void store_out(float* gout, int m0, int rp, int cg,
                                          const float2 (&acc)[8])
{
    float4* d0 = (float4*)(gout + (m0 + 2 * rp) * IMG + (cg << 3));
    float4* d1 = (float4*)(gout + (m0 + 2 * rp + 1) * IMG + (cg << 3));
    d0[0] = make_float4(acc[0].x, acc[1].x, acc[2].x, acc[3].x);
    d0[1] = make_float4(acc[4].x, acc[5].x, acc[6].x, acc[7].x);
    d1[0] = make_float4(acc[0].y, acc[1].y, acc[2].y, acc[3].y);
    d1[1] = make_float4(acc[4].y, acc[5].y, acc[6].y, acc[7].y);
}

// ---------------------------------------------------------------------------
// Boundary paths: one copy each (runtime weights from param constant bank).
// ---------------------------------------------------------------------------
__device__ __noinline__ void v_boundary(
    const float2* __restrict__ scol, float* __restrict__ sv,
    int cp_, int half, int vb, const float* __restrict__ Kf, int ndp)
{
    float2 acc[8] = {};
    float2 ring[8];
    #pragma unroll
    for (int m = 0; m < 8; ++m)
        ring[m] = __ldg(scol + (reflect256(vb + m) << 7));
    #pragma unroll 1
    for (int jj = 0; jj < ndp; jj += 8) {
        #pragma unroll
        for (int u = 0; u < 8; ++u) {
            float W = Kf[jj + u];
            #pragma unroll
            for (int k = 0; k < 8; ++k) {
                float2 r = ring[(u + k) & 7];
                acc[k].x = fmaf(r.x, W, acc[k].x);
                acc[k].y = fmaf(r.y, W, acc[k].y);
            }
            ring[u] = __ldg(scol + (reflect256(vb + jj + u + 8) << 7));
        }
    }
    store_sv(sv, cp_, half, acc);
}

__device__ __noinline__ void h_boundary(
    const float2* __restrict__ sb, float* __restrict__ gout,
    int rp, int cg, int qb, const float* __restrict__ Kf, int ndp, int m0)
{
    float2 acc[8] = {};
    float2 ring[8];
    #pragma unroll
    for (int m = 0; m < 8; ++m)
        ring[m] = sb[reflect256(qb + m) * (SVSTRIDE / 2)];
    #pragma unroll 1
    for (int jj = 0; jj < ndp; jj += 8) {
        #pragma unroll
        for (int u = 0; u < 8; ++u) {
            float W = Kf[jj + u];
            #pragma unroll
            for (int k = 0; k < 8; ++k) {
                float2 r = ring[(u + k) & 7];
                acc[k].x = fmaf(r.x, W, acc[k].x);
                acc[k].y = fmaf(r.y, W, acc[k].y);
            }
            ring[u] = sb[reflect256(qb + jj + u + 8) * (SVSTRIDE / 2)];
        }
    }
    store_out(gout, m0, rp, cg, acc);
}

// ---------------------------------------------------------------------------
// Per-t tile body: V pass (global -> sv transposed), H pass (sv -> out).
// ---------------------------------------------------------------------------
template<int TI>
__device__ __forceinline__ void tile_body(
    const float* __restrict__ img, float* __restrict__ gout, float* sv,
    int tid, int m0, const float* __restrict__ KfT)
{
    constexpr int ND = KT.nd[TI];
    constexpr int RL = KT.rl[TI];
    constexpr int NDP = (ND + 7) & ~7;

    // ---- V phase: thread = column pair x 8 rows ----
    {
        const int cp_ = tid & 127;
        const int half = tid >> 7;
        const float2* scol = (const float2*)img + cp_;
        const int vb = m0 + (half << 3) - RL;
        if (vb >= 0 && vb + ND + 7 <= 255) {
            float2 acc[8] = {};
            float2 ring[8];
            const float2* p = scol + (vb << 7);
            #pragma unroll
            for (int m = 0; m < 8; ++m) ring[m] = __ldg(p + (m << 7));
            VTap<TI, 0>::run(acc, ring, p);
            store_sv(sv, cp_, half, acc);
        } else {
            v_boundary(scol, sv, cp_, half, vb, KfT, NDP);
        }
    }

    __syncthreads();

    // ---- H phase: thread = row pair x 8 columns ----
    {
        const int rp = tid & 7;
        const int cg = tid >> 3;
        const float2* sb = (const float2*)sv + rp;
        const int qb = (cg << 3) - RL;
        if (qb >= 0 && qb + ND + 7 <= 255) {
            float2 acc[8] = {};
            float2 ring[8];
            const float2* p = sb + qb * (SVSTRIDE / 2);
            #pragma unroll
            for (int m = 0; m < 8; ++m) ring[m] = p[m * (SVSTRIDE / 2)];
            HTap<TI, 0>::run(acc, ring, p);
            store_out(gout, m0, rp, cg, acc);
        } else {
            h_boundary(sb, gout, rp, cg, qb, KfT, NDP, m0);
        }
    }
}

// ---------------------------------------------------------------------------
__global__ void __launch_bounds__(256, 4) blur_fused(
    const float* __restrict__ src, float* __restrict__ dst,
    const int* __restrict__ t, const __grid_constant__ BlurParams P)
{
    __shared__ float sv[IMG * SVSTRIDE];

    const int tid = threadIdx.x;
    const int m0 = blockIdx.x << 4;                 // tile's first output row
    const int bc = blockIdx.z * CHAN + blockIdx.y;
    const float* img = src + ((long)bc << 16);
    float* gout = dst + ((long)bc << 16);

    const int tb = t[blockIdx.z];
    if (tb <= 0) {                                  // identity (safety)
        const float4* s4 = (const float4*)(img + (m0 << 8));
        float4* d4 = (float4*)(gout + (m0 << 8));
        #pragma unroll
        for (int i = 0; i < 4; ++i) d4[tid + 256 * i] = s4[tid + 256 * i];
        return;
    }
    const int ti = (tb > NT) ? (NT - 1) : (tb - 1);

    switch (ti) {
#define CASE_TI(TI) case TI: tile_body<TI>(img, gout, sv, tid, m0, P.K[TI]); break;
        CASE_TI(0)  CASE_TI(1)  CASE_TI(2)  CASE_TI(3)  CASE_TI(4)
        CASE_TI(5)  CASE_TI(6)  CASE_TI(7)  CASE_TI(8)  CASE_TI(9)
        CASE_TI(10) CASE_TI(11) CASE_TI(12) CASE_TI(13) CASE_TI(14)
        CASE_TI(15) CASE_TI(16) CASE_TI(17) CASE_TI(18)
#undef CASE_TI
        default: break;
    }
}

// ---------------------------------------------------------------------------
extern "C" void kernel_launch(void* const* d_in, const int* in_sizes, int n_in,
                              void* d_out, int out_size) {
    const float* x = (const float*)d_in[0];
    const int* t = (const int*)d_in[1];
    float* out = (float*)d_out;

    // Runtime weight copy for boundary paths, built from the SAME constexpr
    // table (zero-padded to the 8-multiple the boundary loop uses).
    static BlurParams P = {};
    for (int ti = 0; ti < NT; ++ti) {
        for (int j = 0; j < KW; ++j)
            P.K[ti][j] = (j < KT.nd[ti]) ? KT.w[ti][j] : 0.0f;
    }

    dim3 block(256);
    dim3 grid(IMG / 16, CHAN, BATCH);   // 16 x 3 x 64 = 3072 CTAs
    blur_fused<<<grid, block>>>(x, out, t, P);
}